// round 14
// baseline (speedup 1.0000x reference)
#include <cuda_runtime.h>

#define B_  4
#define L_  100
#define BL_ 400           // B*L
#define DM_ 128           // d_model
#define DI_ 256           // d_inner
#define DS_ 256           // d_state
#define NQD 16            // d-chunks in k_main (16 d's each)

// scratch (device globals; no allocations allowed)
__device__ float g_xpre[BL_ * DI_];
__device__ float g_x   [BL_ * DI_];
__device__ float g_z   [BL_ * DI_];
__device__ float g_Bm  [BL_ * DS_];
__device__ float g_dt  [BL_ * DI_];
__device__ float g_ypart[NQD * BL_ * DS_];  // partial y per d-chunk
__device__ float g_negA[DI_ * DS_];         // -exp(A_log) * log2(e)
// transposed weights: tW[k*N + n] = W[n*K + k]
__device__ float g_tinW [DM_ * 512];   // 128 x 512
__device__ float g_txW  [DI_ * DS_];   // 256 x 256 (first DS rows of x_proj_w)
__device__ float g_tdtW [DI_ * DI_];   // 256 x 256
__device__ float g_toutW[DI_ * DM_];   // 256 x 128

#define LOG2E 1.4426950408889634f

// ---------------------------------------------------------------------------
// prep: blockIdx.y 0..3 -> transpose one weight matrix; y==4 -> negA
__global__ void k_prep(const float* __restrict__ inW,
                       const float* __restrict__ xW,
                       const float* __restrict__ dtW,
                       const float* __restrict__ outW,
                       const float* __restrict__ A_log) {
    if (blockIdx.y == 4) {
        int tid = threadIdx.y * 32 + threadIdx.x;       // 0..255
        for (int i = blockIdx.x * 256 + tid; i < DI_ * DS_; i += 64 * 256)
            g_negA[i] = -__expf(A_log[i]) * LOG2E;
        return;
    }
    __shared__ float tile[32][33];
    const float* src; float* dst; int R, Ccol;   // src is R x Ccol
    switch (blockIdx.y) {
        case 0: src = inW;  dst = g_tinW;  R = 512; Ccol = DM_; break;
        case 1: src = xW;   dst = g_txW;   R = DS_; Ccol = DI_; break;
        case 2: src = dtW;  dst = g_tdtW;  R = DI_; Ccol = DI_; break;
        default:src = outW; dst = g_toutW; R = DM_; Ccol = DI_; break;
    }
    int tilesX = Ccol >> 5;
    int tx = blockIdx.x % tilesX;
    int ty = blockIdx.x / tilesX;
    if (ty >= (R >> 5)) return;
    int c = tx * 32 + threadIdx.x;
    int r = ty * 32 + threadIdx.y;
    #pragma unroll
    for (int j = 0; j < 32; j += 8)
        tile[threadIdx.y + j][threadIdx.x] = src[(r + j) * Ccol + c];
    __syncthreads();
    int oc = ty * 32 + threadIdx.x;
    int orow = tx * 32 + threadIdx.y;
    #pragma unroll
    for (int j = 0; j < 32; j += 8)
        dst[(orow + j) * R + oc] = tile[threadIdx.x][threadIdx.y + j];
}

// ---------------------------------------------------------------------------
// in_proj: grid (100 rowquads, 4 colgroups), 512 threads = 128 cols x 4 k-quarters.
// Weight slice staged in smem: 2 tiles of 64k x 128 cols (32 KB).
__global__ void k_inproj(const float* __restrict__ hs,
                         const float* __restrict__ bias) {
    __shared__ float sh[4][DM_];
    __shared__ float4 sw4[64 * 32];            // 64 k x 128 cols
    float* sw = (float*)sw4;
    __shared__ float spart[4][4][128];
    int r0 = blockIdx.x * 4;
    int cg = blockIdx.y;
    int t  = threadIdx.x;            // 0..511
    {
        int r = t >> 7, k = t & 127;
        sh[r][k] = hs[(r0 + r) * DM_ + k];
    }

    int cl = t & 127;
    int col = cg * 128 + cl;         // 0..511
    int kq = t >> 7;                 // 0..3
    float a0 = 0.f, a1 = 0.f, a2 = 0.f, a3 = 0.f;
    #pragma unroll
    for (int tile = 0; tile < 2; tile++) {
        __syncthreads();
        #pragma unroll
        for (int j = 0; j < 4; j++) {
            int f = j * 512 + t;         // 0..2047 float4s
            int kl = f >> 5, c4 = f & 31;
            sw4[f] = ((const float4*)(g_tinW + (size_t)(tile * 64 + kl) * 512 + cg * 128))[c4];
        }
        __syncthreads();
        #pragma unroll
        for (int kk = 0; kk < 16; kk++) {
            int klocal = kq * 16 + kk;
            int k = tile * 64 + klocal;
            float wv = sw[klocal * 128 + cl];
            a0 = fmaf(wv, sh[0][k], a0);
            a1 = fmaf(wv, sh[1][k], a1);
            a2 = fmaf(wv, sh[2][k], a2);
            a3 = fmaf(wv, sh[3][k], a3);
        }
    }
    spart[kq][0][cl] = a0;
    spart[kq][1][cl] = a1;
    spart[kq][2][cl] = a2;
    spart[kq][3][cl] = a3;
    __syncthreads();

    if (kq == 0) {
        float bv = __ldg(bias + col);
        #pragma unroll
        for (int r = 0; r < 4; r++) {
            float v = (spart[0][r][cl] + spart[1][r][cl])
                    + (spart[2][r][cl] + spart[3][r][cl]) + bv;
            if (col < DI_) g_xpre[(r0 + r) * DI_ + col] = v;
            else           g_z[(r0 + r) * DI_ + (col - DI_)] = v;
        }
    }
}

// ---------------------------------------------------------------------------
// fused conv+silu for 4 rows (only cg0 writes g_x), then Bm / softplus-dt GEMM.
// grid (100 rowquads, 4 colgroups), 512 threads = 128 cols x 4 k-quarters.
// Weight slice staged in smem: 4 tiles of 64k x 128 cols (32 KB).
__global__ void k_convxprojdt(const float* __restrict__ cw,
                              const float* __restrict__ cb,
                              const float* __restrict__ dtb) {
    __shared__ float sx[4][DI_];
    __shared__ float4 sw4[64 * 32];
    float* sw = (float*)sw4;
    __shared__ float spart[4][4][128];
    int r0 = blockIdx.x * 4;
    int cg = blockIdx.y;
    int b  = r0 / L_;
    int l0 = r0 - b * L_;
    int t  = threadIdx.x;            // 0..511

    #pragma unroll
    for (int i = t; i < 4 * DI_; i += 512) {
        int r = i >> 8, c = i & 255;
        int l = l0 + r;
        float acc = __ldg(cb + c);
        #pragma unroll
        for (int j = 0; j < 4; j++) {
            int ll = l - 3 + j;
            if (ll >= 0)
                acc = fmaf(__ldg(cw + c * 4 + j), g_xpre[(b * L_ + ll) * DI_ + c], acc);
        }
        float sg = 1.f / (1.f + __expf(-acc));
        float xv = acc * sg;
        sx[r][c] = xv;
        if (cg == 0) g_x[(r0 + r) * DI_ + c] = xv;
    }

    int cl = t & 127;
    int col = cg * 128 + cl;         // 0..511
    int kq = t >> 7;                 // 0..3
    const float* wbase = (cg < 2) ? (g_txW + cg * 128) : (g_tdtW + (cg - 2) * 128);
    float a0 = 0.f, a1 = 0.f, a2 = 0.f, a3 = 0.f;
    #pragma unroll
    for (int tile = 0; tile < 4; tile++) {
        __syncthreads();
        #pragma unroll
        for (int j = 0; j < 4; j++) {
            int f = j * 512 + t;
            int kl = f >> 5, c4 = f & 31;
            sw4[f] = ((const float4*)(wbase + (size_t)(tile * 64 + kl) * 256))[c4];
        }
        __syncthreads();
        #pragma unroll
        for (int kk = 0; kk < 16; kk++) {
            int klocal = kq * 16 + kk;
            int k = tile * 64 + klocal;
            float wv = sw[klocal * 128 + cl];
            a0 = fmaf(wv, sx[0][k], a0);
            a1 = fmaf(wv, sx[1][k], a1);
            a2 = fmaf(wv, sx[2][k], a2);
            a3 = fmaf(wv, sx[3][k], a3);
        }
    }
    spart[kq][0][cl] = a0;
    spart[kq][1][cl] = a1;
    spart[kq][2][cl] = a2;
    spart[kq][3][cl] = a3;
    __syncthreads();

    if (kq == 0) {
        if (col < DS_) {
            #pragma unroll
            for (int r = 0; r < 4; r++)
                g_Bm[(r0 + r) * DS_ + col] = (spart[0][r][cl] + spart[1][r][cl])
                                           + (spart[2][r][cl] + spart[3][r][cl]);
        } else {
            int j = col - DS_;
            float bv = __ldg(dtb + j);
            #pragma unroll
            for (int r = 0; r < 4; r++) {
                float v = (spart[0][r][cl] + spart[1][r][cl])
                        + (spart[2][r][cl] + spart[3][r][cl]) + bv;
                float sp = (v > 15.f) ? v : log1pf(__expf(v));
                g_dt[(r0 + r) * DI_ + j] = sp;
            }
        }
    }
}

// ---------------------------------------------------------------------------
// main (R12 verbatim): 6400 blocks = (l, qd, b) with b fastest; 256 threads =
// 4 d-subgroups x 64 float4 n-lanes, 4 d's per subgroup (16 d per block).
// All 4 streaming state loads hoisted (MLP); negA prescaled by log2(e);
// __ldcs reads and __stcs writes on the streaming state tensors.
__global__ void __launch_bounds__(256, 5) k_main(
        const float* __restrict__ state,
        const float* __restrict__ C,
        float*       __restrict__ out_state) {
    int bid = blockIdx.x;
    int b  = bid & 3;
    int qd = (bid >> 2) & (NQD - 1);
    int l  = bid >> 6;                // 0..99
    int blr = b * L_ + l;
    int t  = threadIdx.x;             // 0..255
    int g  = t >> 6;                  // subgroup 0..3
    int nq = t & 63;                  // float4 lane over n

    __shared__ float sdt[16];         // dt for this chunk
    if (t < 16) sdt[t] = g_dt[blr * DI_ + qd * 16 + t];
    __syncthreads();

    float4 bm = ((const float4*)(g_Bm + (size_t)blr * DS_))[nq];

    size_t rowbase  = (size_t)blr * DI_ * DS_;
    size_t crowbase = (size_t)l * DI_ * DS_;
    int d0 = qd * 16 + g * 4;

    float4 s[4];
    #pragma unroll
    for (int dd = 0; dd < 4; dd++)
        s[dd] = __ldcs((const float4*)(state + rowbase + (size_t)(d0 + dd) * DS_) + nq);

    float4 acc = make_float4(0.f, 0.f, 0.f, 0.f);
    #pragma unroll
    for (int dd = 0; dd < 4; dd++) {
        int d = d0 + dd;
        float4 na = __ldg((const float4*)(g_negA + (size_t)d * DS_) + nq);
        float4 c  = __ldg((const float4*)(C + crowbase + (size_t)d * DS_) + nq);
        float  dt = sdt[d - qd * 16];
        float4 as;
        as.x = fmaf(s[dd].x, exp2f(dt * na.x), dt * bm.x);
        as.y = fmaf(s[dd].y, exp2f(dt * na.y), dt * bm.y);
        as.z = fmaf(s[dd].z, exp2f(dt * na.z), dt * bm.z);
        as.w = fmaf(s[dd].w, exp2f(dt * na.w), dt * bm.w);
        __stcs((float4*)(out_state + rowbase + (size_t)d * DS_) + nq, as);
        acc.x = fmaf(as.x, c.x, acc.x);
        acc.y = fmaf(as.y, c.y, acc.y);
        acc.z = fmaf(as.z, c.z, acc.z);
        acc.w = fmaf(as.w, c.w, acc.w);
    }

    __shared__ float4 racc[4][64];
    racc[g][nq] = acc;
    __syncthreads();

    if (g == 0) {
        float4 a0 = racc[0][nq], a1 = racc[1][nq],
               a2 = racc[2][nq], a3 = racc[3][nq];
        float4 tot;
        tot.x = (a0.x + a1.x) + (a2.x + a3.x);
        tot.y = (a0.y + a1.y) + (a2.y + a3.y);
        tot.z = (a0.z + a1.z) + (a2.z + a3.z);
        tot.w = (a0.w + a1.w) + (a2.w + a3.w);
        ((float4*)(g_ypart + (size_t)qd * BL_ * DS_ + (size_t)blr * DS_))[nq] = tot;
    }
}

// ---------------------------------------------------------------------------
// out = y @ out_proj_w^T + b with fused epilogue. grid (100 rowquads, 2
// colgroups), 512 threads = 64 cols x 8 k-slices. Weights staged in smem:
// 4 tiles of 64k x 64 cols (16 KB); each slice does 8 k per tile.
__global__ void k_outproj(const float* __restrict__ D1,
                          const float* __restrict__ bias,
                          float* __restrict__ out) {
    __shared__ float sh[4][DI_];
    __shared__ float4 sw4[64 * 16];
    float* sw = (float*)sw4;
    __shared__ float spart[8][4][64];
    int r0 = blockIdx.x * 4;
    int cg = blockIdx.y;
    int t  = threadIdx.x;            // 0..511

    #pragma unroll
    for (int i = t; i < 4 * DI_; i += 512) {
        int r = i >> 8, k = i & 255;
        int idx = (r0 + r) * DI_ + k;
        float tot = 0.f;
        #pragma unroll
        for (int qq = 0; qq < NQD; qq++)
            tot += g_ypart[qq * (BL_ * DS_) + idx];
        float xv = g_x[idx];
        float zv = g_z[idx];
        float y  = fmaf(__ldg(D1 + k), xv, tot);
        float sg = 1.f / (1.f + __expf(-zv));
        sh[r][k] = y * (zv * sg);
    }

    int cl = t & 63;
    int col = cg * 64 + cl;          // 0..127
    int kq = t >> 6;                 // 0..7
    float a0 = 0.f, a1 = 0.f, a2 = 0.f, a3 = 0.f;
    #pragma unroll
    for (int tile = 0; tile < 4; tile++) {
        __syncthreads();
        #pragma unroll
        for (int j = 0; j < 2; j++) {
            int f = j * 512 + t;         // 0..1023 float4s
            int kl = f >> 4, c4 = f & 15;
            sw4[f] = ((const float4*)(g_toutW + (size_t)(tile * 64 + kl) * 128 + cg * 64))[c4];
        }
        __syncthreads();
        #pragma unroll
        for (int kk = 0; kk < 8; kk++) {
            int klocal = kq * 8 + kk;
            int k = tile * 64 + klocal;
            float wv = sw[klocal * 64 + cl];
            a0 = fmaf(wv, sh[0][k], a0);
            a1 = fmaf(wv, sh[1][k], a1);
            a2 = fmaf(wv, sh[2][k], a2);
            a3 = fmaf(wv, sh[3][k], a3);
        }
    }
    spart[kq][0][cl] = a0;
    spart[kq][1][cl] = a1;
    spart[kq][2][cl] = a2;
    spart[kq][3][cl] = a3;
    __syncthreads();

    if (kq == 0) {
        float bv = __ldg(bias + col);
        #pragma unroll
        for (int r = 0; r < 4; r++) {
            float v = bv;
            #pragma unroll
            for (int q = 0; q < 8; q++) v += spart[q][r][cl];
            out[(r0 + r) * DM_ + col] = v;
        }
    }
}

// ---------------------------------------------------------------------------
extern "C" void kernel_launch(void* const* d_in, const int* in_sizes, int n_in,
                              void* d_out, int out_size) {
    const float* hs      = (const float*)d_in[0];   // (4,100,128)
    const float* state   = (const float*)d_in[1];   // (4,100,256,256)
    const float* inW     = (const float*)d_in[2];   // (512,128)
    const float* inB     = (const float*)d_in[3];   // (512,)
    const float* convW   = (const float*)d_in[4];   // (256,1,4)
    const float* convB   = (const float*)d_in[5];   // (256,)
    const float* xW      = (const float*)d_in[6];   // (512,256)
    const float* dtW     = (const float*)d_in[7];   // (256,256)
    const float* dtB     = (const float*)d_in[8];   // (256,)
    const float* A_log   = (const float*)d_in[9];   // (256,256)
    const float* D1      = (const float*)d_in[10];  // (256,)
    const float* Cp      = (const float*)d_in[11];  // (100,256,256)
    const float* outW    = (const float*)d_in[12];  // (128,256)
    const float* outB    = (const float*)d_in[13];  // (128,)

    float* out       = (float*)d_out;               // (4,100,128) first
    float* out_state = out + B_ * L_ * DM_;         // then (4,100,256,256)

    k_prep        <<<dim3(64, 5), dim3(32, 8)>>>(inW, xW, dtW, outW, A_log);
    k_inproj      <<<dim3(L_, 4), 512>>>(hs, inB);
    k_convxprojdt <<<dim3(L_, 4), 512>>>(convW, convB, dtB);
    k_main        <<<BL_ * NQD, 256>>>(state, Cp, out_state);   // 4th (profiled)
    k_outproj     <<<dim3(L_, 2), 512>>>(D1, outB, out);
}

// round 15
// speedup vs baseline: 1.0995x; 1.0995x over previous
#include <cuda_runtime.h>

#define B_  4
#define L_  100
#define BL_ 400           // B*L
#define DM_ 128           // d_model
#define DI_ 256           // d_inner
#define DS_ 256           // d_state
#define NQD 16            // d-chunks in k_main (16 d's each)

// scratch (device globals; no allocations allowed)
__device__ float g_xpre[BL_ * DI_];
__device__ float g_x   [BL_ * DI_];
__device__ float g_z   [BL_ * DI_];
__device__ float g_Bm  [BL_ * DS_];
__device__ float g_dt  [BL_ * DI_];
__device__ float g_ypart[NQD * BL_ * DS_];  // partial y per d-chunk
__device__ float g_negA[DI_ * DS_];         // -exp(A_log) * log2(e)
// transposed weights: tW[k*N + n] = W[n*K + k]
__device__ float g_tinW [DM_ * 512];   // 128 x 512
__device__ float g_txW  [DI_ * DS_];   // 256 x 256 (first DS rows of x_proj_w)
__device__ float g_tdtW [DI_ * DI_];   // 256 x 256
__device__ float g_toutW[DI_ * DM_];   // 256 x 128

#define LOG2E 1.4426950408889634f

// ---------------------------------------------------------------------------
// prep: blockIdx.y 0..3 -> transpose one weight matrix; y==4 -> negA
__global__ void k_prep(const float* __restrict__ inW,
                       const float* __restrict__ xW,
                       const float* __restrict__ dtW,
                       const float* __restrict__ outW,
                       const float* __restrict__ A_log) {
    if (blockIdx.y == 4) {
        int tid = threadIdx.y * 32 + threadIdx.x;       // 0..255
        for (int i = blockIdx.x * 256 + tid; i < DI_ * DS_; i += 64 * 256)
            g_negA[i] = -__expf(A_log[i]) * LOG2E;
        return;
    }
    __shared__ float tile[32][33];
    const float* src; float* dst; int R, Ccol;   // src is R x Ccol
    switch (blockIdx.y) {
        case 0: src = inW;  dst = g_tinW;  R = 512; Ccol = DM_; break;
        case 1: src = xW;   dst = g_txW;   R = DS_; Ccol = DI_; break;
        case 2: src = dtW;  dst = g_tdtW;  R = DI_; Ccol = DI_; break;
        default:src = outW; dst = g_toutW; R = DM_; Ccol = DI_; break;
    }
    int tilesX = Ccol >> 5;
    int tx = blockIdx.x % tilesX;
    int ty = blockIdx.x / tilesX;
    if (ty >= (R >> 5)) return;
    int c = tx * 32 + threadIdx.x;
    int r = ty * 32 + threadIdx.y;
    #pragma unroll
    for (int j = 0; j < 32; j += 8)
        tile[threadIdx.y + j][threadIdx.x] = src[(r + j) * Ccol + c];
    __syncthreads();
    int oc = ty * 32 + threadIdx.x;
    int orow = tx * 32 + threadIdx.y;
    #pragma unroll
    for (int j = 0; j < 32; j += 8)
        dst[(orow + j) * R + oc] = tile[threadIdx.x][threadIdx.y + j];
}

// ---------------------------------------------------------------------------
// in_proj: grid (100 rowquads, 4 colgroups), 512 threads = 128 cols x 4 k-quarters
__global__ void k_inproj(const float* __restrict__ hs,
                         const float* __restrict__ bias) {
    __shared__ float sh[4][DM_];
    __shared__ float spart[4][4][128];
    int r0 = blockIdx.x * 4;
    int cg = blockIdx.y;
    int t  = threadIdx.x;            // 0..511
    {
        int r = t >> 7, k = t & 127;
        sh[r][k] = hs[(r0 + r) * DM_ + k];
    }
    __syncthreads();

    int cl = t & 127;
    int col = cg * 128 + cl;         // 0..511
    int kq = t >> 7;                 // 0..3 (32 k each)
    float a0 = 0.f, a1 = 0.f, a2 = 0.f, a3 = 0.f;
    #pragma unroll
    for (int kk = 0; kk < 32; kk++) {
        int k = kq * 32 + kk;
        float wv = g_tinW[k * 512 + col];
        a0 = fmaf(wv, sh[0][k], a0);
        a1 = fmaf(wv, sh[1][k], a1);
        a2 = fmaf(wv, sh[2][k], a2);
        a3 = fmaf(wv, sh[3][k], a3);
    }
    spart[kq][0][cl] = a0;
    spart[kq][1][cl] = a1;
    spart[kq][2][cl] = a2;
    spart[kq][3][cl] = a3;
    __syncthreads();

    if (kq == 0) {
        float bv = __ldg(bias + col);
        #pragma unroll
        for (int r = 0; r < 4; r++) {
            float v = (spart[0][r][cl] + spart[1][r][cl])
                    + (spart[2][r][cl] + spart[3][r][cl]) + bv;
            if (col < DI_) g_xpre[(r0 + r) * DI_ + col] = v;
            else           g_z[(r0 + r) * DI_ + (col - DI_)] = v;
        }
    }
}

// ---------------------------------------------------------------------------
// fused conv+silu for 4 rows (recomputed per colgroup; only cg0 writes g_x),
// then Bm / softplus-dt GEMM. grid (100 rowquads, 4 colgroups),
// 512 threads = 128 cols x 4 k-quarters (64 k each).
__global__ void k_convxprojdt(const float* __restrict__ cw,
                              const float* __restrict__ cb,
                              const float* __restrict__ dtb) {
    __shared__ float sx[4][DI_];
    __shared__ float spart[4][4][128];
    int r0 = blockIdx.x * 4;
    int cg = blockIdx.y;
    int b  = r0 / L_;
    int l0 = r0 - b * L_;
    int t  = threadIdx.x;            // 0..511

    #pragma unroll
    for (int i = t; i < 4 * DI_; i += 512) {
        int r = i >> 8, c = i & 255;
        int l = l0 + r;
        float acc = __ldg(cb + c);
        #pragma unroll
        for (int j = 0; j < 4; j++) {
            int ll = l - 3 + j;
            if (ll >= 0)
                acc = fmaf(__ldg(cw + c * 4 + j), g_xpre[(b * L_ + ll) * DI_ + c], acc);
        }
        float sg = 1.f / (1.f + __expf(-acc));
        float xv = acc * sg;
        sx[r][c] = xv;
        if (cg == 0) g_x[(r0 + r) * DI_ + c] = xv;
    }
    __syncthreads();

    int cl = t & 127;
    int col = cg * 128 + cl;         // 0..511
    int kq = t >> 7;                 // 0..3 (64 k each)
    const float* wr = (col < DS_) ? (g_txW + col) : (g_tdtW + (col - DS_));
    float a0 = 0.f, a1 = 0.f, a2 = 0.f, a3 = 0.f;
    #pragma unroll 16
    for (int kk = 0; kk < 64; kk++) {
        int k = kq * 64 + kk;
        float wv = wr[k * DI_];
        a0 = fmaf(wv, sx[0][k], a0);
        a1 = fmaf(wv, sx[1][k], a1);
        a2 = fmaf(wv, sx[2][k], a2);
        a3 = fmaf(wv, sx[3][k], a3);
    }
    spart[kq][0][cl] = a0;
    spart[kq][1][cl] = a1;
    spart[kq][2][cl] = a2;
    spart[kq][3][cl] = a3;
    __syncthreads();

    if (kq == 0) {
        if (col < DS_) {
            #pragma unroll
            for (int r = 0; r < 4; r++)
                g_Bm[(r0 + r) * DS_ + col] = (spart[0][r][cl] + spart[1][r][cl])
                                           + (spart[2][r][cl] + spart[3][r][cl]);
        } else {
            int j = col - DS_;
            float bv = __ldg(dtb + j);
            #pragma unroll
            for (int r = 0; r < 4; r++) {
                float v = (spart[0][r][cl] + spart[1][r][cl])
                        + (spart[2][r][cl] + spart[3][r][cl]) + bv;
                float sp = (v > 15.f) ? v : log1pf(__expf(v));
                g_dt[(r0 + r) * DI_ + j] = sp;
            }
        }
    }
}

// ---------------------------------------------------------------------------
// main: 6400 blocks = (l, qd, b) with b fastest; 256 threads =
// 4 d-subgroups x 64 float4 n-lanes, 4 d's per subgroup (16 d per block).
// Streaming state loads AND L2-resident C loads hoisted ahead of the compute
// loop (reg cap raised to 64 via min-blocks 4); negA prescaled by log2(e);
// __ldcs reads / __stcs writes on the streaming state tensors.
__global__ void __launch_bounds__(256, 4) k_main(
        const float* __restrict__ state,
        const float* __restrict__ C,
        float*       __restrict__ out_state) {
    int bid = blockIdx.x;
    int b  = bid & 3;
    int qd = (bid >> 2) & (NQD - 1);
    int l  = bid >> 6;                // 0..99
    int blr = b * L_ + l;
    int t  = threadIdx.x;             // 0..255
    int g  = t >> 6;                  // subgroup 0..3
    int nq = t & 63;                  // float4 lane over n

    __shared__ float sdt[16];         // dt for this chunk
    if (t < 16) sdt[t] = g_dt[blr * DI_ + qd * 16 + t];
    __syncthreads();

    float4 bm = ((const float4*)(g_Bm + (size_t)blr * DS_))[nq];

    size_t rowbase  = (size_t)blr * DI_ * DS_;
    size_t crowbase = (size_t)l * DI_ * DS_;
    int d0 = qd * 16 + g * 4;

    float4 s[4], c[4];
    #pragma unroll
    for (int dd = 0; dd < 4; dd++)
        s[dd] = __ldcs((const float4*)(state + rowbase + (size_t)(d0 + dd) * DS_) + nq);
    #pragma unroll
    for (int dd = 0; dd < 4; dd++)
        c[dd] = __ldg((const float4*)(C + crowbase + (size_t)(d0 + dd) * DS_) + nq);

    float4 acc = make_float4(0.f, 0.f, 0.f, 0.f);
    #pragma unroll
    for (int dd = 0; dd < 4; dd++) {
        int d = d0 + dd;
        float4 na = __ldg((const float4*)(g_negA + (size_t)d * DS_) + nq);
        float  dt = sdt[d - qd * 16];
        float4 as;
        as.x = fmaf(s[dd].x, exp2f(dt * na.x), dt * bm.x);
        as.y = fmaf(s[dd].y, exp2f(dt * na.y), dt * bm.y);
        as.z = fmaf(s[dd].z, exp2f(dt * na.z), dt * bm.z);
        as.w = fmaf(s[dd].w, exp2f(dt * na.w), dt * bm.w);
        __stcs((float4*)(out_state + rowbase + (size_t)d * DS_) + nq, as);
        acc.x = fmaf(as.x, c[dd].x, acc.x);
        acc.y = fmaf(as.y, c[dd].y, acc.y);
        acc.z = fmaf(as.z, c[dd].z, acc.z);
        acc.w = fmaf(as.w, c[dd].w, acc.w);
    }

    __shared__ float4 racc[4][64];
    racc[g][nq] = acc;
    __syncthreads();

    if (g == 0) {
        float4 a0 = racc[0][nq], a1 = racc[1][nq],
               a2 = racc[2][nq], a3 = racc[3][nq];
        float4 tot;
        tot.x = (a0.x + a1.x) + (a2.x + a3.x);
        tot.y = (a0.y + a1.y) + (a2.y + a3.y);
        tot.z = (a0.z + a1.z) + (a2.z + a3.z);
        tot.w = (a0.w + a1.w) + (a2.w + a3.w);
        ((float4*)(g_ypart + (size_t)qd * BL_ * DS_ + (size_t)blr * DS_))[nq] = tot;
    }
}

// ---------------------------------------------------------------------------
// out = y @ out_proj_w^T + b with fused epilogue. grid (100 rowquads, 2
// colgroups), 512 threads = 64 cols x 8 k-slices (32 k each).
__global__ void k_outproj(const float* __restrict__ D1,
                          const float* __restrict__ bias,
                          float* __restrict__ out) {
    __shared__ float sh[4][DI_];
    __shared__ float spart[8][4][64];
    int r0 = blockIdx.x * 4;
    int cg = blockIdx.y;
    int t  = threadIdx.x;            // 0..511

    #pragma unroll
    for (int i = t; i < 4 * DI_; i += 512) {
        int r = i >> 8, k = i & 255;
        int idx = (r0 + r) * DI_ + k;
        float tot = 0.f;
        #pragma unroll
        for (int qq = 0; qq < NQD; qq++)
            tot += g_ypart[qq * (BL_ * DS_) + idx];
        float xv = g_x[idx];
        float zv = g_z[idx];
        float y  = fmaf(__ldg(D1 + k), xv, tot);
        float sg = 1.f / (1.f + __expf(-zv));
        sh[r][k] = y * (zv * sg);
    }
    __syncthreads();

    int cl = t & 63;
    int col = cg * 64 + cl;          // 0..127
    int kq = t >> 6;                 // 0..7 (32 k each)
    float a0 = 0.f, a1 = 0.f, a2 = 0.f, a3 = 0.f;
    #pragma unroll
    for (int kk = 0; kk < 32; kk++) {
        int k = kq * 32 + kk;
        float wv = g_toutW[k * DM_ + col];
        a0 = fmaf(wv, sh[0][k], a0);
        a1 = fmaf(wv, sh[1][k], a1);
        a2 = fmaf(wv, sh[2][k], a2);
        a3 = fmaf(wv, sh[3][k], a3);
    }
    spart[kq][0][cl] = a0;
    spart[kq][1][cl] = a1;
    spart[kq][2][cl] = a2;
    spart[kq][3][cl] = a3;
    __syncthreads();

    if (kq == 0) {
        float bv = __ldg(bias + col);
        #pragma unroll
        for (int r = 0; r < 4; r++) {
            float v = bv;
            #pragma unroll
            for (int q = 0; q < 8; q++) v += spart[q][r][cl];
            out[(r0 + r) * DM_ + col] = v;
        }
    }
}

// ---------------------------------------------------------------------------
extern "C" void kernel_launch(void* const* d_in, const int* in_sizes, int n_in,
                              void* d_out, int out_size) {
    const float* hs      = (const float*)d_in[0];   // (4,100,128)
    const float* state   = (const float*)d_in[1];   // (4,100,256,256)
    const float* inW     = (const float*)d_in[2];   // (512,128)
    const float* inB     = (const float*)d_in[3];   // (512,)
    const float* convW   = (const float*)d_in[4];   // (256,1,4)
    const float* convB   = (const float*)d_in[5];   // (256,)
    const float* xW      = (const float*)d_in[6];   // (512,256)
    const float* dtW     = (const float*)d_in[7];   // (256,256)
    const float* dtB     = (const float*)d_in[8];   // (256,)
    const float* A_log   = (const float*)d_in[9];   // (256,256)
    const float* D1      = (const float*)d_in[10];  // (256,)
    const float* Cp      = (const float*)d_in[11];  // (100,256,256)
    const float* outW    = (const float*)d_in[12];  // (128,256)
    const float* outB    = (const float*)d_in[13];  // (128,)

    float* out       = (float*)d_out;               // (4,100,128) first
    float* out_state = out + B_ * L_ * DM_;         // then (4,100,256,256)

    k_prep        <<<dim3(64, 5), dim3(32, 8)>>>(inW, xW, dtW, outW, A_log);
    k_inproj      <<<dim3(L_, 4), 512>>>(hs, inB);
    k_convxprojdt <<<dim3(L_, 4), 512>>>(convW, convB, dtB);
    k_main        <<<BL_ * NQD, 256>>>(state, Cp, out_state);   // 4th (profiled)
    k_outproj     <<<dim3(L_, 2), 512>>>(D1, outB, out);
}

// round 16
// speedup vs baseline: 1.1358x; 1.0331x over previous
#include <cuda_runtime.h>

#define B_  4
#define L_  100
#define BL_ 400           // B*L
#define DM_ 128           // d_model
#define DI_ 256           // d_inner
#define DS_ 256           // d_state
#define NQD 8             // d-chunks in k_main (32 d's each)

// scratch (device globals; no allocations allowed)
__device__ float g_xpre[BL_ * DI_];
__device__ float g_x   [BL_ * DI_];
__device__ float g_z   [BL_ * DI_];
__device__ float g_Bm  [BL_ * DS_];
__device__ float g_dt  [BL_ * DI_];
__device__ float g_ypart[NQD * BL_ * DS_];  // partial y per d-chunk
__device__ float g_negA[DI_ * DS_];         // -exp(A_log) * log2(e)
// transposed weights: tW[k*N + n] = W[n*K + k]
__device__ float g_tinW [DM_ * 512];   // 128 x 512
__device__ float g_txW  [DI_ * DS_];   // 256 x 256 (first DS rows of x_proj_w)
__device__ float g_tdtW [DI_ * DI_];   // 256 x 256
__device__ float g_toutW[DI_ * DM_];   // 256 x 128

#define LOG2E 1.4426950408889634f

// ---------------------------------------------------------------------------
// prep: blockIdx.y 0..3 -> transpose one weight matrix; y==4 -> negA
__global__ void k_prep(const float* __restrict__ inW,
                       const float* __restrict__ xW,
                       const float* __restrict__ dtW,
                       const float* __restrict__ outW,
                       const float* __restrict__ A_log) {
    if (blockIdx.y == 4) {
        int tid = threadIdx.y * 32 + threadIdx.x;       // 0..255
        for (int i = blockIdx.x * 256 + tid; i < DI_ * DS_; i += 64 * 256)
            g_negA[i] = -__expf(A_log[i]) * LOG2E;
        return;
    }
    __shared__ float tile[32][33];
    const float* src; float* dst; int R, Ccol;   // src is R x Ccol
    switch (blockIdx.y) {
        case 0: src = inW;  dst = g_tinW;  R = 512; Ccol = DM_; break;
        case 1: src = xW;   dst = g_txW;   R = DS_; Ccol = DI_; break;
        case 2: src = dtW;  dst = g_tdtW;  R = DI_; Ccol = DI_; break;
        default:src = outW; dst = g_toutW; R = DM_; Ccol = DI_; break;
    }
    int tilesX = Ccol >> 5;
    int tx = blockIdx.x % tilesX;
    int ty = blockIdx.x / tilesX;
    if (ty >= (R >> 5)) return;
    int c = tx * 32 + threadIdx.x;
    int r = ty * 32 + threadIdx.y;
    #pragma unroll
    for (int j = 0; j < 32; j += 8)
        tile[threadIdx.y + j][threadIdx.x] = src[(r + j) * Ccol + c];
    __syncthreads();
    int oc = ty * 32 + threadIdx.x;
    int orow = tx * 32 + threadIdx.y;
    #pragma unroll
    for (int j = 0; j < 32; j += 8)
        dst[(orow + j) * R + oc] = tile[threadIdx.x][threadIdx.y + j];
}

// ---------------------------------------------------------------------------
// in_proj: grid (100 rowquads, 4 colgroups), 512 threads = 128 cols x 4 k-quarters
__global__ void k_inproj(const float* __restrict__ hs,
                         const float* __restrict__ bias) {
    __shared__ float sh[4][DM_];
    __shared__ float spart[4][4][128];
    int r0 = blockIdx.x * 4;
    int cg = blockIdx.y;
    int t  = threadIdx.x;            // 0..511
    {
        int r = t >> 7, k = t & 127;
        sh[r][k] = hs[(r0 + r) * DM_ + k];
    }
    __syncthreads();

    int cl = t & 127;
    int col = cg * 128 + cl;         // 0..511
    int kq = t >> 7;                 // 0..3 (32 k each)
    float a0 = 0.f, a1 = 0.f, a2 = 0.f, a3 = 0.f;
    #pragma unroll
    for (int kk = 0; kk < 32; kk++) {
        int k = kq * 32 + kk;
        float wv = g_tinW[k * 512 + col];
        a0 = fmaf(wv, sh[0][k], a0);
        a1 = fmaf(wv, sh[1][k], a1);
        a2 = fmaf(wv, sh[2][k], a2);
        a3 = fmaf(wv, sh[3][k], a3);
    }
    spart[kq][0][cl] = a0;
    spart[kq][1][cl] = a1;
    spart[kq][2][cl] = a2;
    spart[kq][3][cl] = a3;
    __syncthreads();

    if (kq == 0) {
        float bv = __ldg(bias + col);
        #pragma unroll
        for (int r = 0; r < 4; r++) {
            float v = (spart[0][r][cl] + spart[1][r][cl])
                    + (spart[2][r][cl] + spart[3][r][cl]) + bv;
            if (col < DI_) g_xpre[(r0 + r) * DI_ + col] = v;
            else           g_z[(r0 + r) * DI_ + (col - DI_)] = v;
        }
    }
}

// ---------------------------------------------------------------------------
// fused conv+silu for 4 rows (recomputed per colgroup; only cg0 writes g_x),
// then Bm / softplus-dt GEMM. grid (100 rowquads, 4 colgroups),
// 512 threads = 128 cols x 4 k-quarters (64 k each).
__global__ void k_convxprojdt(const float* __restrict__ cw,
                              const float* __restrict__ cb,
                              const float* __restrict__ dtb) {
    __shared__ float sx[4][DI_];
    __shared__ float spart[4][4][128];
    int r0 = blockIdx.x * 4;
    int cg = blockIdx.y;
    int b  = r0 / L_;
    int l0 = r0 - b * L_;
    int t  = threadIdx.x;            // 0..511

    #pragma unroll
    for (int i = t; i < 4 * DI_; i += 512) {
        int r = i >> 8, c = i & 255;
        int l = l0 + r;
        float acc = __ldg(cb + c);
        #pragma unroll
        for (int j = 0; j < 4; j++) {
            int ll = l - 3 + j;
            if (ll >= 0)
                acc = fmaf(__ldg(cw + c * 4 + j), g_xpre[(b * L_ + ll) * DI_ + c], acc);
        }
        float sg = 1.f / (1.f + __expf(-acc));
        float xv = acc * sg;
        sx[r][c] = xv;
        if (cg == 0) g_x[(r0 + r) * DI_ + c] = xv;
    }
    __syncthreads();

    int cl = t & 127;
    int col = cg * 128 + cl;         // 0..511
    int kq = t >> 7;                 // 0..3 (64 k each)
    const float* wr = (col < DS_) ? (g_txW + col) : (g_tdtW + (col - DS_));
    float a0 = 0.f, a1 = 0.f, a2 = 0.f, a3 = 0.f;
    #pragma unroll 16
    for (int kk = 0; kk < 64; kk++) {
        int k = kq * 64 + kk;
        float wv = wr[k * DI_];
        a0 = fmaf(wv, sx[0][k], a0);
        a1 = fmaf(wv, sx[1][k], a1);
        a2 = fmaf(wv, sx[2][k], a2);
        a3 = fmaf(wv, sx[3][k], a3);
    }
    spart[kq][0][cl] = a0;
    spart[kq][1][cl] = a1;
    spart[kq][2][cl] = a2;
    spart[kq][3][cl] = a3;
    __syncthreads();

    if (kq == 0) {
        if (col < DS_) {
            #pragma unroll
            for (int r = 0; r < 4; r++)
                g_Bm[(r0 + r) * DS_ + col] = (spart[0][r][cl] + spart[1][r][cl])
                                           + (spart[2][r][cl] + spart[3][r][cl]);
        } else {
            int j = col - DS_;
            float bv = __ldg(dtb + j);
            #pragma unroll
            for (int r = 0; r < 4; r++) {
                float v = (spart[0][r][cl] + spart[1][r][cl])
                        + (spart[2][r][cl] + spart[3][r][cl]) + bv;
                float sp = (v > 15.f) ? v : log1pf(__expf(v));
                g_dt[(r0 + r) * DI_ + j] = sp;
            }
        }
    }
}

// ---------------------------------------------------------------------------
// main: 3200 blocks = (l, qd, b) with b fastest; 256 threads =
// 4 d-subgroups x 64 float4 n-lanes, 8 d's per subgroup (32 d per block).
// ALL 8 streaming state loads hoisted -> 128 B/thread in flight on the
// DRAM stream (1.6x the R12 depth). na/C loaded in-loop (L2-resident).
// negA prescaled by log2(e); __ldcs reads / __stcs writes on state tensors.
__global__ void __launch_bounds__(256, 4) k_main(
        const float* __restrict__ state,
        const float* __restrict__ C,
        float*       __restrict__ out_state) {
    int bid = blockIdx.x;
    int b  = bid & 3;
    int qd = (bid >> 2) & (NQD - 1);
    int l  = bid >> 5;                // 0..99
    int blr = b * L_ + l;
    int t  = threadIdx.x;             // 0..255
    int g  = t >> 6;                  // subgroup 0..3
    int nq = t & 63;                  // float4 lane over n

    __shared__ float sdt[32];         // dt for this chunk
    if (t < 32) sdt[t] = g_dt[blr * DI_ + qd * 32 + t];
    __syncthreads();

    float4 bm = ((const float4*)(g_Bm + (size_t)blr * DS_))[nq];

    size_t rowbase  = (size_t)blr * DI_ * DS_;
    size_t crowbase = (size_t)l * DI_ * DS_;
    int d0 = qd * 32 + g * 8;

    float4 s[8];
    #pragma unroll
    for (int dd = 0; dd < 8; dd++)
        s[dd] = __ldcs((const float4*)(state + rowbase + (size_t)(d0 + dd) * DS_) + nq);

    float4 acc = make_float4(0.f, 0.f, 0.f, 0.f);
    #pragma unroll
    for (int dd = 0; dd < 8; dd++) {
        int d = d0 + dd;
        float4 na = __ldg((const float4*)(g_negA + (size_t)d * DS_) + nq);
        float4 c  = __ldg((const float4*)(C + crowbase + (size_t)d * DS_) + nq);
        float  dt = sdt[d - qd * 32];
        float4 as;
        as.x = fmaf(s[dd].x, exp2f(dt * na.x), dt * bm.x);
        as.y = fmaf(s[dd].y, exp2f(dt * na.y), dt * bm.y);
        as.z = fmaf(s[dd].z, exp2f(dt * na.z), dt * bm.z);
        as.w = fmaf(s[dd].w, exp2f(dt * na.w), dt * bm.w);
        __stcs((float4*)(out_state + rowbase + (size_t)d * DS_) + nq, as);
        acc.x = fmaf(as.x, c.x, acc.x);
        acc.y = fmaf(as.y, c.y, acc.y);
        acc.z = fmaf(as.z, c.z, acc.z);
        acc.w = fmaf(as.w, c.w, acc.w);
    }

    __shared__ float4 racc[4][64];
    racc[g][nq] = acc;
    __syncthreads();

    if (g == 0) {
        float4 a0 = racc[0][nq], a1 = racc[1][nq],
               a2 = racc[2][nq], a3 = racc[3][nq];
        float4 tot;
        tot.x = (a0.x + a1.x) + (a2.x + a3.x);
        tot.y = (a0.y + a1.y) + (a2.y + a3.y);
        tot.z = (a0.z + a1.z) + (a2.z + a3.z);
        tot.w = (a0.w + a1.w) + (a2.w + a3.w);
        ((float4*)(g_ypart + (size_t)qd * BL_ * DS_ + (size_t)blr * DS_))[nq] = tot;
    }
}

// ---------------------------------------------------------------------------
// out = y @ out_proj_w^T + b with fused epilogue. grid (100 rowquads, 2
// colgroups), 512 threads = 64 cols x 8 k-slices (32 k each).
__global__ void k_outproj(const float* __restrict__ D1,
                          const float* __restrict__ bias,
                          float* __restrict__ out) {
    __shared__ float sh[4][DI_];
    __shared__ float spart[8][4][64];
    int r0 = blockIdx.x * 4;
    int cg = blockIdx.y;
    int t  = threadIdx.x;            // 0..511

    #pragma unroll
    for (int i = t; i < 4 * DI_; i += 512) {
        int r = i >> 8, k = i & 255;
        int idx = (r0 + r) * DI_ + k;
        float tot = 0.f;
        #pragma unroll
        for (int qq = 0; qq < NQD; qq++)
            tot += g_ypart[qq * (BL_ * DS_) + idx];
        float xv = g_x[idx];
        float zv = g_z[idx];
        float y  = fmaf(__ldg(D1 + k), xv, tot);
        float sg = 1.f / (1.f + __expf(-zv));
        sh[r][k] = y * (zv * sg);
    }
    __syncthreads();

    int cl = t & 63;
    int col = cg * 64 + cl;          // 0..127
    int kq = t >> 6;                 // 0..7 (32 k each)
    float a0 = 0.f, a1 = 0.f, a2 = 0.f, a3 = 0.f;
    #pragma unroll
    for (int kk = 0; kk < 32; kk++) {
        int k = kq * 32 + kk;
        float wv = g_toutW[k * DM_ + col];
        a0 = fmaf(wv, sh[0][k], a0);
        a1 = fmaf(wv, sh[1][k], a1);
        a2 = fmaf(wv, sh[2][k], a2);
        a3 = fmaf(wv, sh[3][k], a3);
    }
    spart[kq][0][cl] = a0;
    spart[kq][1][cl] = a1;
    spart[kq][2][cl] = a2;
    spart[kq][3][cl] = a3;
    __syncthreads();

    if (kq == 0) {
        float bv = __ldg(bias + col);
        #pragma unroll
        for (int r = 0; r < 4; r++) {
            float v = bv;
            #pragma unroll
            for (int q = 0; q < 8; q++) v += spart[q][r][cl];
            out[(r0 + r) * DM_ + col] = v;
        }
    }
}

// ---------------------------------------------------------------------------
extern "C" void kernel_launch(void* const* d_in, const int* in_sizes, int n_in,
                              void* d_out, int out_size) {
    const float* hs      = (const float*)d_in[0];   // (4,100,128)
    const float* state   = (const float*)d_in[1];   // (4,100,256,256)
    const float* inW     = (const float*)d_in[2];   // (512,128)
    const float* inB     = (const float*)d_in[3];   // (512,)
    const float* convW   = (const float*)d_in[4];   // (256,1,4)
    const float* convB   = (const float*)d_in[5];   // (256,)
    const float* xW      = (const float*)d_in[6];   // (512,256)
    const float* dtW     = (const float*)d_in[7];   // (256,256)
    const float* dtB     = (const float*)d_in[8];   // (256,)
    const float* A_log   = (const float*)d_in[9];   // (256,256)
    const float* D1      = (const float*)d_in[10];  // (256,)
    const float* Cp      = (const float*)d_in[11];  // (100,256,256)
    const float* outW    = (const float*)d_in[12];  // (128,256)
    const float* outB    = (const float*)d_in[13];  // (128,)

    float* out       = (float*)d_out;               // (4,100,128) first
    float* out_state = out + B_ * L_ * DM_;         // then (4,100,256,256)

    k_prep        <<<dim3(64, 5), dim3(32, 8)>>>(inW, xW, dtW, outW, A_log);
    k_inproj      <<<dim3(L_, 4), 512>>>(hs, inB);
    k_convxprojdt <<<dim3(L_, 4), 512>>>(convW, convB, dtB);
    k_main        <<<BL_ * NQD, 256>>>(state, Cp, out_state);   // 4th (profiled)
    k_outproj     <<<dim3(L_, 2), 512>>>(D1, outB, out);
}